// round 1
// baseline (speedup 1.0000x reference)
#include <cuda_runtime.h>
#include <math.h>

// Problem constants (fixed shapes from reference setup_inputs)
#define NTOK   8192      // B*S = 2*4096
#define SEQ    4096
#define DMODEL 1024
#define NEXP   16
#define DBOT   256
#define DTASK  32
#define RQUOTA 64

// ---------------- device scratch (no allocations allowed) ----------------
__device__ float  g_H[NTOK * DBOT];       // x @ W_down
__device__ float  g_Z[NTOK * DBOT];       // gelu(H) * comb coefficients
__device__ float  g_L[NTOK * NEXP];       // raw x @ Wr[:D]
__device__ float  g_gmask[NEXP * DBOT];   // gate[e] if j in top-64(topo[e]) else 0
__device__ float  g_cs[NEXP];             // colsum of Wr[:D]
__device__ float  g_base[2 * NEXP];       // per-batch task logit + bias
__device__ float  g_stats[4];             // mu0, rstd0, mu1, rstd1
__device__ double g_part[2 * 64 * 2];     // per-block partial (sum, sumsq)
__device__ int    g_sel[NTOK * 2];        // top-2 expert ids
__device__ float  g_w[NTOK * 2];          // top-2 softmax weights

// ---------------- kernel 1: per-batch sum / sumsq partials ----------------
__global__ void k_stats(const float* __restrict__ x) {
    int b = blockIdx.y;
    const float4* xb = reinterpret_cast<const float4*>(x + (size_t)b * SEQ * DMODEL);
    const int nvec = SEQ * DMODEL / 4;  // 1048576
    double s = 0.0, q = 0.0;
    for (int i = blockIdx.x * blockDim.x + threadIdx.x; i < nvec;
         i += gridDim.x * blockDim.x) {
        float4 v = xb[i];
        s += (double)v.x; q += (double)v.x * v.x;
        s += (double)v.y; q += (double)v.y * v.y;
        s += (double)v.z; q += (double)v.z * v.z;
        s += (double)v.w; q += (double)v.w * v.w;
    }
    __shared__ double rs[256], rq[256];
    rs[threadIdx.x] = s; rq[threadIdx.x] = q;
    __syncthreads();
    for (int st = 128; st > 0; st >>= 1) {
        if (threadIdx.x < st) {
            rs[threadIdx.x] += rs[threadIdx.x + st];
            rq[threadIdx.x] += rq[threadIdx.x + st];
        }
        __syncthreads();
    }
    if (threadIdx.x == 0) {
        g_part[(b * 64 + blockIdx.x) * 2 + 0] = rs[0];
        g_part[(b * 64 + blockIdx.x) * 2 + 1] = rq[0];
    }
}

// ---------------- kernel 2: finalize stats, router constants, topo masks ----------------
__global__ void k_setup(const int* __restrict__ task_id,
                        const float* __restrict__ task_emb,
                        const float* __restrict__ Wr,
                        const float* __restrict__ br,
                        const float* __restrict__ topo) {
    int tid = threadIdx.x;
    __shared__ double rd[256];

    // ---- batch mean / rstd ----
    for (int b = 0; b < 2; b++) {
        double s = (tid < 64) ? g_part[(b * 64 + tid) * 2 + 0] : 0.0;
        double q = (tid < 64) ? g_part[(b * 64 + tid) * 2 + 1] : 0.0;
        rd[tid] = s; __syncthreads();
        for (int st = 128; st > 0; st >>= 1) {
            if (tid < st) rd[tid] += rd[tid + st];
            __syncthreads();
        }
        double S = rd[0]; __syncthreads();
        rd[tid] = q; __syncthreads();
        for (int st = 128; st > 0; st >>= 1) {
            if (tid < st) rd[tid] += rd[tid + st];
            __syncthreads();
        }
        double Q = rd[0]; __syncthreads();
        if (tid == 0) {
            const double cnt = (double)SEQ * DMODEL;
            double mu  = S / cnt;
            double var = Q / cnt - mu * mu;
            g_stats[b * 2 + 0] = (float)mu;
            g_stats[b * 2 + 1] = (float)(1.0 / sqrt(var + 1e-5));
        }
        __syncthreads();
    }

    // ---- column sums of Wr[:D] ----
    {
        __shared__ float rf[256];
        int e = tid & 15, lane = tid >> 4;
        float p = 0.f;
        for (int d = lane; d < DMODEL; d += 16) p += Wr[d * NEXP + e];
        rf[tid] = p; __syncthreads();
        if (tid < 16) {
            float s2 = 0.f;
            for (int l = 0; l < 16; l++) s2 += rf[l * 16 + tid];
            g_cs[tid] = s2;
        }
        __syncthreads();
    }

    // ---- per-batch task logits + bias ----
    if (tid < 32) {
        int b = tid >> 4, e = tid & 15;
        int tI = task_id[b];
        float v = br[e];
        for (int t = 0; t < DTASK; t++)
            v += task_emb[tI * DTASK + t] * Wr[(DMODEL + t) * NEXP + e];
        g_base[b * NEXP + e] = v;
    }
    __syncthreads();

    // ---- topo top-64 mask + gate per expert ----
    __shared__ float row[256];
    __shared__ float rs[256];
    for (int e = 0; e < NEXP; e++) {
        row[tid] = topo[e * DBOT + tid];
        __syncthreads();
        float v = row[tid];
        int rank = 0;
        for (int i = 0; i < DBOT; i++) {
            float u = row[i];
            rank += (u > v) || (u == v && i < tid);
        }
        int sel = (rank < RQUOTA);
        rs[tid] = sel ? 1.f / (1.f + expf(-v)) : 0.f;
        __syncthreads();
        for (int st = 128; st > 0; st >>= 1) {
            if (tid < st) rs[tid] += rs[tid + st];
            __syncthreads();
        }
        float gate = rs[0] / (float)RQUOTA;
        g_gmask[e * DBOT + tid] = sel ? gate : 0.f;
        __syncthreads();
    }
}

// ---------------- kernel 3: GEMM1  [8192,1024] x [1024, 256|16] -> g_H, g_L ----------------
// Logical N = 320 (5 tiles of 64): cols 0..255 -> W_down / g_H, 256..271 -> Wr[:D] / g_L
__global__ void k_gemm1(const float* __restrict__ x,
                        const float* __restrict__ Wd,
                        const float* __restrict__ Wr) {
    __shared__ float As[16][64];
    __shared__ float Bs[16][64];
    int tid = threadIdx.x;
    int tx = tid & 15, ty = tid >> 4;
    int row0 = blockIdx.y * 64;
    int col0 = blockIdx.x * 64;

    float acc[4][4] = {};
    int am = tid >> 2, ak = (tid & 3) * 4;
    int bk = tid >> 4, bn = (tid & 15) * 4;
    int n = col0 + bn;

    for (int k0 = 0; k0 < DMODEL; k0 += 16) {
        float4 av = *reinterpret_cast<const float4*>(
            &x[(size_t)(row0 + am) * DMODEL + k0 + ak]);
        As[ak + 0][am] = av.x; As[ak + 1][am] = av.y;
        As[ak + 2][am] = av.z; As[ak + 3][am] = av.w;

        float4 bv;
        if (n < DBOT)
            bv = *reinterpret_cast<const float4*>(&Wd[(k0 + bk) * DBOT + n]);
        else if (n < DBOT + NEXP)
            bv = *reinterpret_cast<const float4*>(&Wr[(k0 + bk) * NEXP + (n - DBOT)]);
        else
            bv = make_float4(0.f, 0.f, 0.f, 0.f);
        *reinterpret_cast<float4*>(&Bs[bk][bn]) = bv;
        __syncthreads();

#pragma unroll
        for (int kk = 0; kk < 16; kk++) {
            float4 b4 = *reinterpret_cast<const float4*>(&Bs[kk][tx * 4]);
            float a0 = As[kk][ty * 4 + 0], a1 = As[kk][ty * 4 + 1];
            float a2 = As[kk][ty * 4 + 2], a3 = As[kk][ty * 4 + 3];
            acc[0][0] += a0 * b4.x; acc[0][1] += a0 * b4.y; acc[0][2] += a0 * b4.z; acc[0][3] += a0 * b4.w;
            acc[1][0] += a1 * b4.x; acc[1][1] += a1 * b4.y; acc[1][2] += a1 * b4.z; acc[1][3] += a1 * b4.w;
            acc[2][0] += a2 * b4.x; acc[2][1] += a2 * b4.y; acc[2][2] += a2 * b4.z; acc[2][3] += a2 * b4.w;
            acc[3][0] += a3 * b4.x; acc[3][1] += a3 * b4.y; acc[3][2] += a3 * b4.z; acc[3][3] += a3 * b4.w;
        }
        __syncthreads();
    }

#pragma unroll
    for (int i = 0; i < 4; i++) {
        int m = row0 + ty * 4 + i;
#pragma unroll
        for (int j = 0; j < 4; j++) {
            int cc = col0 + tx * 4 + j;
            if (cc < DBOT)
                g_H[m * DBOT + cc] = acc[i][j];
            else if (cc < DBOT + NEXP)
                g_L[m * NEXP + (cc - DBOT)] = acc[i][j];
        }
    }
}

// ---------------- kernel 4: per-token routing (top-2 + softmax) ----------------
__global__ void k_route() {
    int nIdx = blockIdx.x * blockDim.x + threadIdx.x;
    if (nIdx >= NTOK) return;
    int b = nIdx >> 12;
    float mu = g_stats[b * 2 + 0];
    float rstd = g_stats[b * 2 + 1];
    float best = -1e30f, sec = -1e30f;
    int i0 = 0, i1 = 0;
#pragma unroll
    for (int e = 0; e < NEXP; e++) {
        float l = rstd * (g_L[nIdx * NEXP + e] - mu * g_cs[e]) + g_base[b * NEXP + e];
        if (l > best) { sec = best; i1 = i0; best = l; i0 = e; }
        else if (l > sec) { sec = l; i1 = e; }
    }
    float e1 = expf(sec - best);
    float inv = 1.f / (1.f + e1);
    g_sel[nIdx * 2 + 0] = i0;
    g_sel[nIdx * 2 + 1] = i1;
    g_w[nIdx * 2 + 0] = inv;
    g_w[nIdx * 2 + 1] = e1 * inv;
}

// ---------------- kernel 5: z = gelu(H) * (w0*gmask[e0] + w1*gmask[e1]) ----------------
__global__ void k_z() {
    for (int idx = blockIdx.x * blockDim.x + threadIdx.x; idx < NTOK * DBOT;
         idx += gridDim.x * blockDim.x) {
        int nn = idx >> 8;
        int j = idx & 255;
        float h = g_H[idx];
        float inner = 0.7978845608028654f * (h + 0.044715f * h * h * h);
        float a = 0.5f * h * (1.f + tanhf(inner));
        float c = g_w[nn * 2 + 0] * g_gmask[g_sel[nn * 2 + 0] * DBOT + j]
                + g_w[nn * 2 + 1] * g_gmask[g_sel[nn * 2 + 1] * DBOT + j];
        g_Z[idx] = a * c;
    }
}

// ---------------- kernel 6: GEMM2  [8192,256] x [256,1024] -> y ----------------
__global__ void k_gemm2(const float* __restrict__ B, float* __restrict__ C) {
    __shared__ float As[16][64];
    __shared__ float Bs[16][64];
    int tid = threadIdx.x;
    int tx = tid & 15, ty = tid >> 4;
    int row0 = blockIdx.y * 64;
    int col0 = blockIdx.x * 64;

    float acc[4][4] = {};
    int am = tid >> 2, ak = (tid & 3) * 4;
    int bk = tid >> 4, bn = (tid & 15) * 4;

    for (int k0 = 0; k0 < DBOT; k0 += 16) {
        float4 av = *reinterpret_cast<const float4*>(
            &g_Z[(size_t)(row0 + am) * DBOT + k0 + ak]);
        As[ak + 0][am] = av.x; As[ak + 1][am] = av.y;
        As[ak + 2][am] = av.z; As[ak + 3][am] = av.w;
        *reinterpret_cast<float4*>(&Bs[bk][bn]) =
            *reinterpret_cast<const float4*>(&B[(k0 + bk) * DMODEL + col0 + bn]);
        __syncthreads();

#pragma unroll
        for (int kk = 0; kk < 16; kk++) {
            float4 b4 = *reinterpret_cast<const float4*>(&Bs[kk][tx * 4]);
            float a0 = As[kk][ty * 4 + 0], a1 = As[kk][ty * 4 + 1];
            float a2 = As[kk][ty * 4 + 2], a3 = As[kk][ty * 4 + 3];
            acc[0][0] += a0 * b4.x; acc[0][1] += a0 * b4.y; acc[0][2] += a0 * b4.z; acc[0][3] += a0 * b4.w;
            acc[1][0] += a1 * b4.x; acc[1][1] += a1 * b4.y; acc[1][2] += a1 * b4.z; acc[1][3] += a1 * b4.w;
            acc[2][0] += a2 * b4.x; acc[2][1] += a2 * b4.y; acc[2][2] += a2 * b4.z; acc[2][3] += a2 * b4.w;
            acc[3][0] += a3 * b4.x; acc[3][1] += a3 * b4.y; acc[3][2] += a3 * b4.z; acc[3][3] += a3 * b4.w;
        }
        __syncthreads();
    }

#pragma unroll
    for (int i = 0; i < 4; i++) {
        float4 o = make_float4(acc[i][0], acc[i][1], acc[i][2], acc[i][3]);
        *reinterpret_cast<float4*>(
            &C[(size_t)(row0 + ty * 4 + i) * DMODEL + col0 + tx * 4]) = o;
    }
}

// ---------------- launch ----------------
extern "C" void kernel_launch(void* const* d_in, const int* in_sizes, int n_in,
                              void* d_out, int out_size) {
    const float* x        = (const float*)d_in[0];
    const int*   task_id  = (const int*)d_in[1];
    const float* task_emb = (const float*)d_in[2];
    const float* Wr       = (const float*)d_in[3];
    const float* br       = (const float*)d_in[4];
    const float* W_down   = (const float*)d_in[5];
    const float* W_up     = (const float*)d_in[6];
    const float* topo     = (const float*)d_in[7];
    float* y = (float*)d_out;

    k_stats<<<dim3(64, 2), 256>>>(x);
    k_setup<<<1, 256>>>(task_id, task_emb, Wr, br, topo);
    k_gemm1<<<dim3(5, 128), 256>>>(x, W_down, Wr);
    k_route<<<32, 256>>>();
    k_z<<<2048, 256>>>();
    k_gemm2<<<dim3(16, 128), 256>>>(W_up, y);
}

// round 3
// speedup vs baseline: 1.6797x; 1.6797x over previous
#include <cuda_runtime.h>
#include <cuda_bf16.h>
#include <math.h>
#include <stdint.h>

// Problem constants (fixed shapes from reference setup_inputs)
#define NTOK   8192      // B*S = 2*4096
#define SEQ    4096
#define DMODEL 1024
#define NEXP   16
#define DBOT   256
#define DTASK  32
#define RQUOTA 64

#define SA 40            // smem row stride in bf16 elems (80B, conflict-free + 16B aligned)

// ================= device scratch =================
__device__ float  g_H[NTOK * DBOT];
__device__ float  g_Z[NTOK * DBOT];
__device__ float  g_L[NTOK * NEXP];
__device__ float  g_gmask[NEXP * DBOT];
__device__ float  g_cs[NEXP];
__device__ float  g_base[2 * NEXP];
__device__ float  g_stats[4];
__device__ double g_part[2 * 64 * 2];
__device__ int    g_sel[NTOK * 2];
__device__ float  g_w[NTOK * 2];
// combined GEMM1 B: rows 0..255 = W_down^T, 256..271 = Wr[:D]^T, 272..383 zero pad
__device__ __nv_bfloat16 g_B1T_h[384 * DMODEL];
__device__ __nv_bfloat16 g_B1T_l[384 * DMODEL];
// GEMM2 B: W_up^T [1024][256]
__device__ __nv_bfloat16 g_B2T_h[DMODEL * DBOT];
__device__ __nv_bfloat16 g_B2T_l[DMODEL * DBOT];

// ================= kernel 1: per-batch sum / sumsq partials =================
__global__ void k_stats(const float* __restrict__ x) {
    int b = blockIdx.y;
    const float4* xb = reinterpret_cast<const float4*>(x + (size_t)b * SEQ * DMODEL);
    const int nvec = SEQ * DMODEL / 4;
    double s = 0.0, q = 0.0;
    for (int i = blockIdx.x * blockDim.x + threadIdx.x; i < nvec;
         i += gridDim.x * blockDim.x) {
        float4 v = xb[i];
        s += (double)v.x; q += (double)v.x * v.x;
        s += (double)v.y; q += (double)v.y * v.y;
        s += (double)v.z; q += (double)v.z * v.z;
        s += (double)v.w; q += (double)v.w * v.w;
    }
    __shared__ double rs[256], rq[256];
    rs[threadIdx.x] = s; rq[threadIdx.x] = q;
    __syncthreads();
    for (int st = 128; st > 0; st >>= 1) {
        if (threadIdx.x < st) {
            rs[threadIdx.x] += rs[threadIdx.x + st];
            rq[threadIdx.x] += rq[threadIdx.x + st];
        }
        __syncthreads();
    }
    if (threadIdx.x == 0) {
        g_part[(b * 64 + blockIdx.x) * 2 + 0] = rs[0];
        g_part[(b * 64 + blockIdx.x) * 2 + 1] = rq[0];
    }
}

// ================= kernel 2: finalize stats, router constants, topo masks =================
__global__ void k_setup(const int* __restrict__ task_id,
                        const float* __restrict__ task_emb,
                        const float* __restrict__ Wr,
                        const float* __restrict__ br,
                        const float* __restrict__ topo) {
    int tid = threadIdx.x;
    __shared__ double rd[256];

    for (int b = 0; b < 2; b++) {
        double s = (tid < 64) ? g_part[(b * 64 + tid) * 2 + 0] : 0.0;
        double q = (tid < 64) ? g_part[(b * 64 + tid) * 2 + 1] : 0.0;
        rd[tid] = s; __syncthreads();
        for (int st = 128; st > 0; st >>= 1) {
            if (tid < st) rd[tid] += rd[tid + st];
            __syncthreads();
        }
        double S = rd[0]; __syncthreads();
        rd[tid] = q; __syncthreads();
        for (int st = 128; st > 0; st >>= 1) {
            if (tid < st) rd[tid] += rd[tid + st];
            __syncthreads();
        }
        double Q = rd[0]; __syncthreads();
        if (tid == 0) {
            const double cnt = (double)SEQ * DMODEL;
            double mu  = S / cnt;
            double var = Q / cnt - mu * mu;
            g_stats[b * 2 + 0] = (float)mu;
            g_stats[b * 2 + 1] = (float)(1.0 / sqrt(var + 1e-5));
        }
        __syncthreads();
    }

    {
        __shared__ float rf[256];
        int e = tid & 15, lane = tid >> 4;
        float p = 0.f;
        for (int d = lane; d < DMODEL; d += 16) p += Wr[d * NEXP + e];
        rf[tid] = p; __syncthreads();
        if (tid < 16) {
            float s2 = 0.f;
            for (int l = 0; l < 16; l++) s2 += rf[l * 16 + tid];
            g_cs[tid] = s2;
        }
        __syncthreads();
    }

    if (tid < 32) {
        int b = tid >> 4, e = tid & 15;
        int tI = task_id[b];
        float v = br[e];
        for (int t = 0; t < DTASK; t++)
            v += task_emb[tI * DTASK + t] * Wr[(DMODEL + t) * NEXP + e];
        g_base[b * NEXP + e] = v;
    }
    __syncthreads();

    __shared__ float row[256];
    __shared__ float rs[256];
    for (int e = 0; e < NEXP; e++) {
        row[tid] = topo[e * DBOT + tid];
        __syncthreads();
        float v = row[tid];
        int rank = 0;
        for (int i = 0; i < DBOT; i++) {
            float u = row[i];
            rank += (u > v) || (u == v && i < tid);
        }
        int sel = (rank < RQUOTA);
        rs[tid] = sel ? 1.f / (1.f + expf(-v)) : 0.f;
        __syncthreads();
        for (int st = 128; st > 0; st >>= 1) {
            if (tid < st) rs[tid] += rs[tid + st];
            __syncthreads();
        }
        float gate = rs[0] / (float)RQUOTA;
        g_gmask[e * DBOT + tid] = sel ? gate : 0.f;
        __syncthreads();
    }
}

// ================= transpose + bf16-split prep =================
// sel 0: W_down [1024,256] -> B1T rows [0,256)
// sel 1: Wr[:1024] [.,16]  -> B1T rows [256,272)
// sel 2: W_up [256,1024]   -> B2T rows [0,1024)
__global__ void k_tsplit(const float* __restrict__ in, int R, int C, int sel) {
    __nv_bfloat16* outh;
    __nv_bfloat16* outl;
    if (sel == 0)      { outh = g_B1T_h;              outl = g_B1T_l; }
    else if (sel == 1) { outh = g_B1T_h + 256 * DMODEL; outl = g_B1T_l + 256 * DMODEL; }
    else               { outh = g_B2T_h;              outl = g_B2T_l; }

    __shared__ float t[32][33];
    int c0 = blockIdx.x * 32, r0 = blockIdx.y * 32;
    int tx = threadIdx.x, ty = threadIdx.y;
#pragma unroll
    for (int i = 0; i < 32; i += 8) {
        int r = r0 + ty + i, c = c0 + tx;
        t[ty + i][tx] = (r < R && c < C) ? in[(size_t)r * C + c] : 0.f;
    }
    __syncthreads();
#pragma unroll
    for (int i = 0; i < 32; i += 8) {
        int c = c0 + ty + i, r = r0 + tx;
        if (c < C && r < R) {
            float v = t[tx][ty + i];
            __nv_bfloat16 h = __float2bfloat16(v);
            __nv_bfloat16 l = __float2bfloat16(v - __bfloat162float(h));
            outh[(size_t)c * R + r] = h;
            outl[(size_t)c * R + r] = l;
        }
    }
}

// ================= mma.sync helpers =================
__device__ __forceinline__ void mma16816(float* d, const uint32_t* a,
                                         const uint32_t* b) {
    asm volatile(
        "mma.sync.aligned.m16n8k16.row.col.f32.bf16.bf16.f32 "
        "{%0,%1,%2,%3}, {%4,%5,%6,%7}, {%8,%9}, {%0,%1,%2,%3};"
        : "+f"(d[0]), "+f"(d[1]), "+f"(d[2]), "+f"(d[3])
        : "r"(a[0]), "r"(a[1]), "r"(a[2]), "r"(a[3]), "r"(b[0]), "r"(b[1]));
}

__device__ __forceinline__ void split2(float x, float y, uint32_t& h, uint32_t& l) {
    __nv_bfloat162 hh = __float22bfloat162_rn(make_float2(x, y));
    float rx = x - __bfloat162float(hh.x);
    float ry = y - __bfloat162float(hh.y);
    __nv_bfloat162 ll = __float22bfloat162_rn(make_float2(rx, ry));
    h = *reinterpret_cast<uint32_t*>(&hh);
    l = *reinterpret_cast<uint32_t*>(&ll);
}

// ================= tcgen-free tensor GEMM core (bf16x3 split, fp32 acc) =================
// C[row0:+128, n0:+128] = A[row0:,:K] @ B^T (B stored [N][K] row-major, split h/l)
// mode 0: plain store to C (ldc). mode 1: GEMM1 scatter (g_H cols<256, g_L cols 256..271)
__device__ __forceinline__ void gemm_body(
    const float* __restrict__ A, int lda,
    const __nv_bfloat16* __restrict__ Bh, const __nv_bfloat16* __restrict__ Bl,
    int K, int n0, int row0, int mode, float* __restrict__ C, int ldc)
{
    __shared__ __align__(16) __nv_bfloat16 sAh[128 * SA];
    __shared__ __align__(16) __nv_bfloat16 sAl[128 * SA];
    __shared__ __align__(16) __nv_bfloat16 sBh[128 * SA];
    __shared__ __align__(16) __nv_bfloat16 sBl[128 * SA];

    const int tid = threadIdx.x;
    const int wid = tid >> 5, lane = tid & 31;
    const int wm = wid >> 2, wn = wid & 3;           // warp grid 2x4
    const int g = lane >> 2, tig = lane & 3;

    const bool active = (mode == 0) || (n0 + wn * 32 < 272);

    float acc[4][4][4];
#pragma unroll
    for (int i = 0; i < 4; i++)
#pragma unroll
        for (int j = 0; j < 4; j++)
#pragma unroll
            for (int k = 0; k < 4; k++) acc[i][j][k] = 0.f;

    // prefetch registers
    float4 pa[4];
    uint4  pbh[2], pbl[2];

    const int ar = tid >> 3, aj = tid & 7;   // A fill coords (32 rows/pass, float4)
    const int br = tid >> 2, bj = tid & 3;   // B fill coords (64 rows/pass, uint4=8bf16)

    const int nch = K >> 5;

    // initial prefetch (chunk 0)
    {
        const float* ap = A + (size_t)(row0 + ar) * lda + aj * 4;
#pragma unroll
        for (int p = 0; p < 4; p++)
            pa[p] = *reinterpret_cast<const float4*>(ap + (size_t)p * 32 * lda);
        const __nv_bfloat16* bph = Bh + (size_t)(n0 + br) * K + bj * 8;
        const __nv_bfloat16* bpl = Bl + (size_t)(n0 + br) * K + bj * 8;
#pragma unroll
        for (int p = 0; p < 2; p++) {
            pbh[p] = *reinterpret_cast<const uint4*>(bph + (size_t)p * 64 * K);
            pbl[p] = *reinterpret_cast<const uint4*>(bpl + (size_t)p * 64 * K);
        }
    }

    const uint32_t* uAh = reinterpret_cast<const uint32_t*>(sAh);
    const uint32_t* uAl = reinterpret_cast<const uint32_t*>(sAl);
    const uint32_t* uBh = reinterpret_cast<const uint32_t*>(sBh);
    const uint32_t* uBl = reinterpret_cast<const uint32_t*>(sBl);

    for (int ch = 0; ch < nch; ch++) {
        // ---- store prefetched chunk into smem (A: split on the fly) ----
#pragma unroll
        for (int p = 0; p < 4; p++) {
            uint32_t h0, l0, h1, l1;
            split2(pa[p].x, pa[p].y, h0, l0);
            split2(pa[p].z, pa[p].w, h1, l1);
            int r = p * 32 + ar;
            reinterpret_cast<uint2*>(sAh)[r * 10 + aj] = make_uint2(h0, h1);
            reinterpret_cast<uint2*>(sAl)[r * 10 + aj] = make_uint2(l0, l1);
        }
#pragma unroll
        for (int p = 0; p < 2; p++) {
            int r = p * 64 + br;
            reinterpret_cast<uint4*>(sBh)[r * 5 + bj] = pbh[p];
            reinterpret_cast<uint4*>(sBl)[r * 5 + bj] = pbl[p];
        }
        __syncthreads();

        // ---- prefetch next chunk (overlaps with MMA below) ----
        if (ch + 1 < nch) {
            int k0 = (ch + 1) * 32;
            const float* ap = A + (size_t)(row0 + ar) * lda + k0 + aj * 4;
#pragma unroll
            for (int p = 0; p < 4; p++)
                pa[p] = *reinterpret_cast<const float4*>(ap + (size_t)p * 32 * lda);
            const __nv_bfloat16* bph = Bh + (size_t)(n0 + br) * K + k0 + bj * 8;
            const __nv_bfloat16* bpl = Bl + (size_t)(n0 + br) * K + k0 + bj * 8;
#pragma unroll
            for (int p = 0; p < 2; p++) {
                pbh[p] = *reinterpret_cast<const uint4*>(bph + (size_t)p * 64 * K);
                pbl[p] = *reinterpret_cast<const uint4*>(bpl + (size_t)p * 64 * K);
            }
        }

        // ---- MMA phase ----
        if (active) {
#pragma unroll
            for (int ks = 0; ks < 2; ks++) {
                const int kb = ks * 8;   // u32 offset within row
                uint32_t ah[4][4], bb[4][2];
                // load Ah frags
#pragma unroll
                for (int mt = 0; mt < 4; mt++) {
                    int base = (wm * 64 + mt * 16 + g) * 20 + kb + tig;
                    ah[mt][0] = uAh[base];
                    ah[mt][1] = uAh[base + 160];
                    ah[mt][2] = uAh[base + 4];
                    ah[mt][3] = uAh[base + 164];
                }
                // Bh frags + Ah*Bh
#pragma unroll
                for (int nt = 0; nt < 4; nt++) {
                    int base = (wn * 32 + nt * 8 + g) * 20 + kb + tig;
                    bb[nt][0] = uBh[base];
                    bb[nt][1] = uBh[base + 4];
                }
#pragma unroll
                for (int mt = 0; mt < 4; mt++)
#pragma unroll
                    for (int nt = 0; nt < 4; nt++)
                        mma16816(acc[mt][nt], ah[mt], bb[nt]);
                // Bl frags + Ah*Bl
#pragma unroll
                for (int nt = 0; nt < 4; nt++) {
                    int base = (wn * 32 + nt * 8 + g) * 20 + kb + tig;
                    bb[nt][0] = uBl[base];
                    bb[nt][1] = uBl[base + 4];
                }
#pragma unroll
                for (int mt = 0; mt < 4; mt++)
#pragma unroll
                    for (int nt = 0; nt < 4; nt++)
                        mma16816(acc[mt][nt], ah[mt], bb[nt]);
                // Al frags + Al*Bh
#pragma unroll
                for (int mt = 0; mt < 4; mt++) {
                    int base = (wm * 64 + mt * 16 + g) * 20 + kb + tig;
                    ah[mt][0] = uAl[base];
                    ah[mt][1] = uAl[base + 160];
                    ah[mt][2] = uAl[base + 4];
                    ah[mt][3] = uAl[base + 164];
                }
#pragma unroll
                for (int nt = 0; nt < 4; nt++) {
                    int base = (wn * 32 + nt * 8 + g) * 20 + kb + tig;
                    bb[nt][0] = uBh[base];
                    bb[nt][1] = uBh[base + 4];
                }
#pragma unroll
                for (int mt = 0; mt < 4; mt++)
#pragma unroll
                    for (int nt = 0; nt < 4; nt++)
                        mma16816(acc[mt][nt], ah[mt], bb[nt]);
            }
        }
        __syncthreads();
    }

    // ---- epilogue ----
    if (!active) return;
#pragma unroll
    for (int mt = 0; mt < 4; mt++) {
        int r = row0 + wm * 64 + mt * 16 + g;
#pragma unroll
        for (int nt = 0; nt < 4; nt++) {
            int col = n0 + wn * 32 + nt * 8 + 2 * tig;
            float2 v0 = make_float2(acc[mt][nt][0], acc[mt][nt][1]);
            float2 v1 = make_float2(acc[mt][nt][2], acc[mt][nt][3]);
            if (mode == 0) {
                *reinterpret_cast<float2*>(&C[(size_t)r * ldc + col]) = v0;
                *reinterpret_cast<float2*>(&C[(size_t)(r + 8) * ldc + col]) = v1;
            } else {
                if (col < DBOT) {
                    *reinterpret_cast<float2*>(&g_H[(size_t)r * DBOT + col]) = v0;
                    *reinterpret_cast<float2*>(&g_H[(size_t)(r + 8) * DBOT + col]) = v1;
                } else if (col < DBOT + NEXP) {
                    int c = col - DBOT;
                    *reinterpret_cast<float2*>(&g_L[(size_t)r * NEXP + c]) = v0;
                    *reinterpret_cast<float2*>(&g_L[(size_t)(r + 8) * NEXP + c]) = v1;
                }
            }
        }
    }
}

// GEMM1: x[8192,1024] @ B1T^T  (N-tiles: 0,1 -> g_H; 2 -> g_L)
__global__ void __launch_bounds__(256) k_gemm1(const float* __restrict__ x) {
    gemm_body(x, DMODEL, g_B1T_h, g_B1T_l, DMODEL,
              blockIdx.x * 128, blockIdx.y * 128, 1, nullptr, 0);
}

// GEMM2: Z[8192,256] @ B2T^T -> y[8192,1024]
__global__ void __launch_bounds__(256) k_gemm2(float* __restrict__ y) {
    gemm_body(g_Z, DBOT, g_B2T_h, g_B2T_l, DBOT,
              blockIdx.x * 128, blockIdx.y * 128, 0, y, DMODEL);
}

// ================= routing (top-2 + softmax) =================
__global__ void k_route() {
    int nIdx = blockIdx.x * blockDim.x + threadIdx.x;
    if (nIdx >= NTOK) return;
    int b = nIdx >> 12;
    float mu = g_stats[b * 2 + 0];
    float rstd = g_stats[b * 2 + 1];
    float best = -1e30f, sec = -1e30f;
    int i0 = 0, i1 = 0;
#pragma unroll
    for (int e = 0; e < NEXP; e++) {
        float l = rstd * (g_L[nIdx * NEXP + e] - mu * g_cs[e]) + g_base[b * NEXP + e];
        if (l > best) { sec = best; i1 = i0; best = l; i0 = e; }
        else if (l > sec) { sec = l; i1 = e; }
    }
    float e1 = expf(sec - best);
    float inv = 1.f / (1.f + e1);
    g_sel[nIdx * 2 + 0] = i0;
    g_sel[nIdx * 2 + 1] = i1;
    g_w[nIdx * 2 + 0] = inv;
    g_w[nIdx * 2 + 1] = e1 * inv;
}

// ================= z = gelu(H) * combine =================
__global__ void k_z() {
    for (int idx = blockIdx.x * blockDim.x + threadIdx.x; idx < NTOK * DBOT;
         idx += gridDim.x * blockDim.x) {
        int nn = idx >> 8;
        int j = idx & 255;
        float h = g_H[idx];
        float inner = 0.7978845608028654f * (h + 0.044715f * h * h * h);
        float a = 0.5f * h * (1.f + tanhf(inner));
        float c = g_w[nn * 2 + 0] * g_gmask[g_sel[nn * 2 + 0] * DBOT + j]
                + g_w[nn * 2 + 1] * g_gmask[g_sel[nn * 2 + 1] * DBOT + j];
        g_Z[idx] = a * c;
    }
}

// ================= launch =================
extern "C" void kernel_launch(void* const* d_in, const int* in_sizes, int n_in,
                              void* d_out, int out_size) {
    const float* x        = (const float*)d_in[0];
    const int*   task_id  = (const int*)d_in[1];
    const float* task_emb = (const float*)d_in[2];
    const float* Wr       = (const float*)d_in[3];
    const float* br       = (const float*)d_in[4];
    const float* W_down   = (const float*)d_in[5];
    const float* W_up     = (const float*)d_in[6];
    const float* topo     = (const float*)d_in[7];
    float* y = (float*)d_out;

    k_stats<<<dim3(64, 2), 256>>>(x);
    k_setup<<<1, 256>>>(task_id, task_emb, Wr, br, topo);
    // weight transpose + bf16 split
    k_tsplit<<<dim3(8, 32),  dim3(32, 8)>>>(W_down, DMODEL, DBOT, 0);
    k_tsplit<<<dim3(1, 32),  dim3(32, 8)>>>(Wr,     DMODEL, NEXP, 1);
    k_tsplit<<<dim3(32, 8),  dim3(32, 8)>>>(W_up,   DBOT, DMODEL, 2);
    // GEMM1: H = x @ W_down and L = x @ Wr[:D]
    k_gemm1<<<dim3(3, 64), 256>>>(x);
    k_route<<<32, 256>>>();
    k_z<<<2048, 256>>>();
    // GEMM2: y = Z @ W_up
    k_gemm2<<<dim3(8, 64), 256>>>(y);
}

// round 4
// speedup vs baseline: 1.7895x; 1.0654x over previous
#include <cuda_runtime.h>
#include <cuda_bf16.h>
#include <math.h>
#include <stdint.h>

// Problem constants (fixed shapes from reference setup_inputs)
#define NTOK   8192      // B*S = 2*4096
#define SEQ    4096
#define DMODEL 1024
#define NEXP   16
#define DBOT   256
#define DTASK  32
#define RQUOTA 64

#define SA 40            // smem row stride in bf16 elems (80B, conflict-free)
#define BUFB 40960       // bytes per smem buffer (4 arrays * 128*40*2)
#define OFF_AL 10240
#define OFF_BH 20480
#define OFF_BL 30720

// ================= device scratch =================
__device__ float  g_H[NTOK * DBOT];
__device__ float  g_L[NTOK * NEXP];
__device__ float  g_gmask[NEXP * DBOT];
__device__ float  g_cs[NEXP];
__device__ float  g_base[2 * NEXP];
__device__ float  g_stats[4];
__device__ double g_part[2 * 64 * 2];
__device__ int    g_sel[NTOK * 2];
__device__ float  g_w[NTOK * 2];
// pre-split activations
__device__ __nv_bfloat16 g_Xh[NTOK * DMODEL];
__device__ __nv_bfloat16 g_Xl[NTOK * DMODEL];
__device__ __nv_bfloat16 g_Zh[NTOK * DBOT];
__device__ __nv_bfloat16 g_Zl[NTOK * DBOT];
// combined GEMM1 B: rows 0..255 = W_down^T, 256..271 = Wr[:D]^T, 272..383 zero
__device__ __nv_bfloat16 g_B1T_h[384 * DMODEL];
__device__ __nv_bfloat16 g_B1T_l[384 * DMODEL];
// GEMM2 B: W_up^T [1024][256]
__device__ __nv_bfloat16 g_B2T_h[DMODEL * DBOT];
__device__ __nv_bfloat16 g_B2T_l[DMODEL * DBOT];

// ================= helpers =================
__device__ __forceinline__ uint32_t smem_u32(const void* p) {
    uint32_t a;
    asm("{ .reg .u64 t; cvta.to.shared.u64 t, %1; cvt.u32.u64 %0, t; }" : "=r"(a) : "l"(p));
    return a;
}
#define LDSM4(d, addr) \
    asm volatile("ldmatrix.sync.aligned.m8n8.x4.shared.b16 {%0,%1,%2,%3}, [%4];" \
        : "=r"((d)[0]), "=r"((d)[1]), "=r"((d)[2]), "=r"((d)[3]) : "r"(addr))

__device__ __forceinline__ void mma16816(float* d, const uint32_t* a,
                                         const uint32_t* b) {
    asm volatile(
        "mma.sync.aligned.m16n8k16.row.col.f32.bf16.bf16.f32 "
        "{%0,%1,%2,%3}, {%4,%5,%6,%7}, {%8,%9}, {%0,%1,%2,%3};"
        : "+f"(d[0]), "+f"(d[1]), "+f"(d[2]), "+f"(d[3])
        : "r"(a[0]), "r"(a[1]), "r"(a[2]), "r"(a[3]), "r"(b[0]), "r"(b[1]));
}

__device__ __forceinline__ void split2(float x, float y, uint32_t& h, uint32_t& l) {
    __nv_bfloat162 hh = __float22bfloat162_rn(make_float2(x, y));
    float rx = x - __bfloat162float(hh.x);
    float ry = y - __bfloat162float(hh.y);
    __nv_bfloat162 ll = __float22bfloat162_rn(make_float2(rx, ry));
    h = *reinterpret_cast<uint32_t*>(&hh);
    l = *reinterpret_cast<uint32_t*>(&ll);
}

// ================= kernel 1: stats partials + x split =================
__global__ void k_stats(const float* __restrict__ x) {
    int b = blockIdx.y;
    const float4* xb = reinterpret_cast<const float4*>(x + (size_t)b * SEQ * DMODEL);
    uint2* xh = reinterpret_cast<uint2*>(g_Xh + (size_t)b * SEQ * DMODEL);
    uint2* xl = reinterpret_cast<uint2*>(g_Xl + (size_t)b * SEQ * DMODEL);
    const int nvec = SEQ * DMODEL / 4;
    double s = 0.0, q = 0.0;
    for (int i = blockIdx.x * blockDim.x + threadIdx.x; i < nvec;
         i += gridDim.x * blockDim.x) {
        float4 v = xb[i];
        s += (double)v.x; q += (double)v.x * v.x;
        s += (double)v.y; q += (double)v.y * v.y;
        s += (double)v.z; q += (double)v.z * v.z;
        s += (double)v.w; q += (double)v.w * v.w;
        uint32_t h0, l0, h1, l1;
        split2(v.x, v.y, h0, l0);
        split2(v.z, v.w, h1, l1);
        xh[i] = make_uint2(h0, h1);
        xl[i] = make_uint2(l0, l1);
    }
    __shared__ double rs[256], rq[256];
    rs[threadIdx.x] = s; rq[threadIdx.x] = q;
    __syncthreads();
    for (int st = 128; st > 0; st >>= 1) {
        if (threadIdx.x < st) {
            rs[threadIdx.x] += rs[threadIdx.x + st];
            rq[threadIdx.x] += rq[threadIdx.x + st];
        }
        __syncthreads();
    }
    if (threadIdx.x == 0) {
        g_part[(b * 64 + blockIdx.x) * 2 + 0] = rs[0];
        g_part[(b * 64 + blockIdx.x) * 2 + 1] = rq[0];
    }
}

// ================= kernel 2: finalize stats, router constants, topo masks =================
__global__ void k_setup(const int* __restrict__ task_id,
                        const float* __restrict__ task_emb,
                        const float* __restrict__ Wr,
                        const float* __restrict__ br,
                        const float* __restrict__ topo) {
    int tid = threadIdx.x;
    __shared__ double rd[256];

    for (int b = 0; b < 2; b++) {
        double s = (tid < 64) ? g_part[(b * 64 + tid) * 2 + 0] : 0.0;
        double q = (tid < 64) ? g_part[(b * 64 + tid) * 2 + 1] : 0.0;
        rd[tid] = s; __syncthreads();
        for (int st = 128; st > 0; st >>= 1) {
            if (tid < st) rd[tid] += rd[tid + st];
            __syncthreads();
        }
        double S = rd[0]; __syncthreads();
        rd[tid] = q; __syncthreads();
        for (int st = 128; st > 0; st >>= 1) {
            if (tid < st) rd[tid] += rd[tid + st];
            __syncthreads();
        }
        double Q = rd[0]; __syncthreads();
        if (tid == 0) {
            const double cnt = (double)SEQ * DMODEL;
            double mu  = S / cnt;
            double var = Q / cnt - mu * mu;
            g_stats[b * 2 + 0] = (float)mu;
            g_stats[b * 2 + 1] = (float)(1.0 / sqrt(var + 1e-5));
        }
        __syncthreads();
    }

    {
        __shared__ float rf[256];
        int e = tid & 15, lane = tid >> 4;
        float p = 0.f;
        for (int d = lane; d < DMODEL; d += 16) p += Wr[d * NEXP + e];
        rf[tid] = p; __syncthreads();
        if (tid < 16) {
            float s2 = 0.f;
            for (int l = 0; l < 16; l++) s2 += rf[l * 16 + tid];
            g_cs[tid] = s2;
        }
        __syncthreads();
    }

    if (tid < 32) {
        int b = tid >> 4, e = tid & 15;
        int tI = task_id[b];
        float v = br[e];
        for (int t = 0; t < DTASK; t++)
            v += task_emb[tI * DTASK + t] * Wr[(DMODEL + t) * NEXP + e];
        g_base[b * NEXP + e] = v;
    }
    __syncthreads();

    __shared__ float row[256];
    __shared__ float rs[256];
    for (int e = 0; e < NEXP; e++) {
        row[tid] = topo[e * DBOT + tid];
        __syncthreads();
        float v = row[tid];
        int rank = 0;
        for (int i = 0; i < DBOT; i++) {
            float u = row[i];
            rank += (u > v) || (u == v && i < tid);
        }
        int sel = (rank < RQUOTA);
        rs[tid] = sel ? 1.f / (1.f + expf(-v)) : 0.f;
        __syncthreads();
        for (int st = 128; st > 0; st >>= 1) {
            if (tid < st) rs[tid] += rs[tid + st];
            __syncthreads();
        }
        float gate = rs[0] / (float)RQUOTA;
        g_gmask[e * DBOT + tid] = sel ? gate : 0.f;
        __syncthreads();
    }
}

// ================= transpose + bf16-split weights =================
__global__ void k_tsplit(const float* __restrict__ in, int R, int C, int sel) {
    __nv_bfloat16* outh;
    __nv_bfloat16* outl;
    if (sel == 0)      { outh = g_B1T_h;                outl = g_B1T_l; }
    else if (sel == 1) { outh = g_B1T_h + 256 * DMODEL; outl = g_B1T_l + 256 * DMODEL; }
    else               { outh = g_B2T_h;                outl = g_B2T_l; }

    __shared__ float t[32][33];
    int c0 = blockIdx.x * 32, r0 = blockIdx.y * 32;
    int tx = threadIdx.x, ty = threadIdx.y;
#pragma unroll
    for (int i = 0; i < 32; i += 8) {
        int r = r0 + ty + i, c = c0 + tx;
        t[ty + i][tx] = (r < R && c < C) ? in[(size_t)r * C + c] : 0.f;
    }
    __syncthreads();
#pragma unroll
    for (int i = 0; i < 32; i += 8) {
        int c = c0 + ty + i, r = r0 + tx;
        if (c < C && r < R) {
            float v = t[tx][ty + i];
            __nv_bfloat16 h = __float2bfloat16(v);
            __nv_bfloat16 l = __float2bfloat16(v - __bfloat162float(h));
            outh[(size_t)c * R + r] = h;
            outl[(size_t)c * R + r] = l;
        }
    }
}

// ================= tensor GEMM core: presplit bf16 A/B, ldmatrix, dbuf =================
// C[row0:+128, n0:+128] = A @ B^T (A [M][K] h/l, B [N][K] h/l)
// MODE 0: plain store (C, ldc). MODE 1: GEMM1 scatter (g_H <256, g_L 256..271)
template <int MODE>
__device__ __forceinline__ void gemm_body(
    const __nv_bfloat16* __restrict__ Ah, const __nv_bfloat16* __restrict__ Al,
    const __nv_bfloat16* __restrict__ Bh, const __nv_bfloat16* __restrict__ Bl,
    int K, int n0, int row0, float* __restrict__ C, int ldc)
{
    extern __shared__ char smem[];
    const int tid = threadIdx.x;
    const int wid = tid >> 5, lane = tid & 31;
    const int wm = wid >> 2, wn = wid & 3;    // 2x4 warp grid
    const bool active = (MODE == 0) || (n0 + wn * 32 < 272);

    float acc[4][4][4] = {};

    const int r4 = tid >> 2, j4 = tid & 3;    // uint4 fill: 64 rows/pass, 2 passes
    const uint32_t sb = smem_u32(smem);
    // ldmatrix per-thread base offsets (bytes)
    const uint32_t a_off = ((wm * 64 + (lane & 15)) * SA + (lane >> 4) * 8) * 2;
    const uint32_t b_off = ((wn * 32 + (lane >> 4) * 8 + (lane & 7)) * SA
                            + ((lane >> 3) & 1) * 8) * 2;

    uint4 pAh[2], pAl[2], pBh[2], pBl[2];
    const int nch = K >> 5;

#define PREF(k0) do { \
    _Pragma("unroll") \
    for (int p = 0; p < 2; p++) { \
        size_t ai = (size_t)(row0 + p * 64 + r4) * K + (k0) + j4 * 8; \
        pAh[p] = *reinterpret_cast<const uint4*>(Ah + ai); \
        pAl[p] = *reinterpret_cast<const uint4*>(Al + ai); \
        size_t bi = (size_t)(n0 + p * 64 + r4) * K + (k0) + j4 * 8; \
        pBh[p] = *reinterpret_cast<const uint4*>(Bh + bi); \
        pBl[p] = *reinterpret_cast<const uint4*>(Bl + bi); \
    } } while (0)

    PREF(0);

    for (int ch = 0; ch < nch; ch++) {
        char* buf = smem + (ch & 1) * BUFB;
#pragma unroll
        for (int p = 0; p < 2; p++) {
            int ri = (p * 64 + r4) * 5 + j4;
            reinterpret_cast<uint4*>(buf)[ri]            = pAh[p];
            reinterpret_cast<uint4*>(buf + OFF_AL)[ri]   = pAl[p];
            reinterpret_cast<uint4*>(buf + OFF_BH)[ri]   = pBh[p];
            reinterpret_cast<uint4*>(buf + OFF_BL)[ri]   = pBl[p];
        }
        __syncthreads();
        if (ch + 1 < nch) PREF((ch + 1) * 32);

        if (active) {
            uint32_t ab = sb + (ch & 1) * BUFB;
#pragma unroll
            for (int ks = 0; ks < 2; ks++) {
                const uint32_t koff = ks * 32;  // 16 elems * 2B
                uint32_t ah[4][4], al[4][4], bb[4][2];
#pragma unroll
                for (int mt = 0; mt < 4; mt++) {
                    uint32_t addr = ab + a_off + mt * (16 * SA * 2) + koff;
                    LDSM4(ah[mt], addr);
                    LDSM4(al[mt], addr + OFF_AL);
                }
                // Bh: two x4 loads cover 4 n-tiles
#pragma unroll
                for (int p = 0; p < 2; p++) {
                    uint32_t addr = ab + OFF_BH + b_off + p * (16 * SA * 2) + koff;
                    LDSM4(&bb[2 * p][0], addr);
                }
#pragma unroll
                for (int mt = 0; mt < 4; mt++)
#pragma unroll
                    for (int nt = 0; nt < 4; nt++)
                        mma16816(acc[mt][nt], ah[mt], bb[nt]);
#pragma unroll
                for (int mt = 0; mt < 4; mt++)
#pragma unroll
                    for (int nt = 0; nt < 4; nt++)
                        mma16816(acc[mt][nt], al[mt], bb[nt]);
                // Bl
#pragma unroll
                for (int p = 0; p < 2; p++) {
                    uint32_t addr = ab + OFF_BL + b_off + p * (16 * SA * 2) + koff;
                    LDSM4(&bb[2 * p][0], addr);
                }
#pragma unroll
                for (int mt = 0; mt < 4; mt++)
#pragma unroll
                    for (int nt = 0; nt < 4; nt++)
                        mma16816(acc[mt][nt], ah[mt], bb[nt]);
            }
        }
    }
#undef PREF

    if (!active) return;
    const int g = lane >> 2, tig = lane & 3;
#pragma unroll
    for (int mt = 0; mt < 4; mt++) {
        int r = row0 + wm * 64 + mt * 16 + g;
#pragma unroll
        for (int nt = 0; nt < 4; nt++) {
            int col = n0 + wn * 32 + nt * 8 + 2 * tig;
            float2 v0 = make_float2(acc[mt][nt][0], acc[mt][nt][1]);
            float2 v1 = make_float2(acc[mt][nt][2], acc[mt][nt][3]);
            if (MODE == 0) {
                *reinterpret_cast<float2*>(&C[(size_t)r * ldc + col]) = v0;
                *reinterpret_cast<float2*>(&C[(size_t)(r + 8) * ldc + col]) = v1;
            } else {
                if (col < DBOT) {
                    *reinterpret_cast<float2*>(&g_H[(size_t)r * DBOT + col]) = v0;
                    *reinterpret_cast<float2*>(&g_H[(size_t)(r + 8) * DBOT + col]) = v1;
                } else if (col < DBOT + NEXP) {
                    int c = col - DBOT;
                    *reinterpret_cast<float2*>(&g_L[(size_t)r * NEXP + c]) = v0;
                    *reinterpret_cast<float2*>(&g_L[(size_t)(r + 8) * NEXP + c]) = v1;
                }
            }
        }
    }
}

__global__ void __launch_bounds__(256) k_gemm1() {
    gemm_body<1>(g_Xh, g_Xl, g_B1T_h, g_B1T_l, DMODEL,
                 blockIdx.x * 128, blockIdx.y * 128, nullptr, 0);
}
__global__ void __launch_bounds__(256) k_gemm2(float* __restrict__ y) {
    gemm_body<0>(g_Zh, g_Zl, g_B2T_h, g_B2T_l, DBOT,
                 blockIdx.x * 128, blockIdx.y * 128, y, DMODEL);
}

// ================= routing (top-2 + softmax) =================
__global__ void k_route() {
    int nIdx = blockIdx.x * blockDim.x + threadIdx.x;
    if (nIdx >= NTOK) return;
    int b = nIdx >> 12;
    float mu = g_stats[b * 2 + 0];
    float rstd = g_stats[b * 2 + 1];
    float best = -1e30f, sec = -1e30f;
    int i0 = 0, i1 = 0;
#pragma unroll
    for (int e = 0; e < NEXP; e++) {
        float l = rstd * (g_L[nIdx * NEXP + e] - mu * g_cs[e]) + g_base[b * NEXP + e];
        if (l > best) { sec = best; i1 = i0; best = l; i0 = e; }
        else if (l > sec) { sec = l; i1 = e; }
    }
    float e1 = expf(sec - best);
    float inv = 1.f / (1.f + e1);
    g_sel[nIdx * 2 + 0] = i0;
    g_sel[nIdx * 2 + 1] = i1;
    g_w[nIdx * 2 + 0] = inv;
    g_w[nIdx * 2 + 1] = e1 * inv;
}

// ================= z = gelu(H) * combine, split to bf16 h/l =================
__global__ void k_z() {
    uint32_t* zh = reinterpret_cast<uint32_t*>(g_Zh);
    uint32_t* zl = reinterpret_cast<uint32_t*>(g_Zl);
    for (int i2 = blockIdx.x * blockDim.x + threadIdx.x; i2 < NTOK * DBOT / 2;
         i2 += gridDim.x * blockDim.x) {
        int idx = i2 * 2;
        int nn = idx >> 8;
        int j = idx & 255;
        float2 hv = *reinterpret_cast<const float2*>(&g_H[idx]);
        float w0 = g_w[nn * 2 + 0], w1 = g_w[nn * 2 + 1];
        const float* m0 = &g_gmask[g_sel[nn * 2 + 0] * DBOT + j];
        const float* m1 = &g_gmask[g_sel[nn * 2 + 1] * DBOT + j];
        float z[2];
#pragma unroll
        for (int t = 0; t < 2; t++) {
            float h = (t == 0) ? hv.x : hv.y;
            float inner = 0.7978845608028654f * (h + 0.044715f * h * h * h);
            float a = 0.5f * h * (1.f + tanhf(inner));
            z[t] = a * (w0 * m0[t] + w1 * m1[t]);
        }
        uint32_t h, l;
        split2(z[0], z[1], h, l);
        zh[i2] = h;
        zl[i2] = l;
    }
}

// ================= launch =================
extern "C" void kernel_launch(void* const* d_in, const int* in_sizes, int n_in,
                              void* d_out, int out_size) {
    const float* x        = (const float*)d_in[0];
    const int*   task_id  = (const int*)d_in[1];
    const float* task_emb = (const float*)d_in[2];
    const float* Wr       = (const float*)d_in[3];
    const float* br       = (const float*)d_in[4];
    const float* W_down   = (const float*)d_in[5];
    const float* W_up     = (const float*)d_in[6];
    const float* topo     = (const float*)d_in[7];
    float* y = (float*)d_out;

    cudaFuncSetAttribute(k_gemm1, cudaFuncAttributeMaxDynamicSharedMemorySize, 2 * BUFB);
    cudaFuncSetAttribute(k_gemm2, cudaFuncAttributeMaxDynamicSharedMemorySize, 2 * BUFB);

    k_stats<<<dim3(64, 2), 256>>>(x);
    k_setup<<<1, 256>>>(task_id, task_emb, Wr, br, topo);
    k_tsplit<<<dim3(8, 32),  dim3(32, 8)>>>(W_down, DMODEL, DBOT, 0);
    k_tsplit<<<dim3(1, 32),  dim3(32, 8)>>>(Wr,     DMODEL, NEXP, 1);
    k_tsplit<<<dim3(32, 8),  dim3(32, 8)>>>(W_up,   DBOT, DMODEL, 2);
    k_gemm1<<<dim3(3, 64), 256, 2 * BUFB>>>();
    k_route<<<32, 256>>>();
    k_z<<<1024, 256>>>();
    k_gemm2<<<dim3(8, 64), 256, 2 * BUFB>>>(y);
}